// round 15
// baseline (speedup 1.0000x reference)
#include <cuda_runtime.h>
#include <cuda_bf16.h>
#include <cuda_fp16.h>
#include <cstdint>
#include <cstring>

#define N_NODES 50000
#define N_EDGES 800000
#define EPS 1e-5f
#define LO_SCALE 2048.0f
#define LO_INV   (1.0f / 2048.0f)

#define TILE_M 128
#define NTILES ((N_NODES + TILE_M - 1) / TILE_M)   // 391
#define MMA_GRID 148
#define PREP_BLOCKS ((N_NODES * 16 + 255) / 256)   // 3125

// SMEM layout (bytes): X hi/lo + all four W images resident
#define SM_XHI   0
#define SM_XLO   32768
#define SM_W0HI  65536
#define SM_W0LO  98304
#define SM_W1HI  131072
#define SM_W1LO  163840
#define SM_STATS 196608
#define SM_TOTAL (196608 + 1024)

// Scratch (__device__ globals, allocation-free rule).
// g_cnt is zero at module load and re-zeroed by scan_kernel every launch.
__device__ float g_bufA[N_NODES * 128];
__device__ float g_bufB[N_NODES * 128];
__device__ uint4 g_xh16[N_NODES * 16];  // fp16 activations (gather + GEMM hi)
__device__ uint4 g_xlo[N_NODES * 16];   // fp16 residual x2048 (GEMM lo)
__device__ uint4 g_agghi[N_NODES * 16];
__device__ uint4 g_agglo[N_NODES * 16];
__device__ int   g_rowptr[N_NODES + 1];
__device__ int   g_cnt[2 * N_NODES];    // sharded histogram (self-cleaning)
__device__ int   g_cursor[N_NODES];
__device__ int   g_csrsrc[N_EDGES];
__device__ float g_invdeg[N_NODES];
__device__ float g_stats[512];          // [0:256) layer1, [256:512) layer2
__device__ uint4 g_wthi[2 * 2048];      // pass-major W^T f16 hi images (32KB each)
__device__ uint4 g_wtlo[2 * 2048];      // f16 residual x2048

// ===========================================================================
// CSR build
// ===========================================================================
__global__ void hist_kernel(const int2* __restrict__ dst2, int* __restrict__ cnt) {
    int e = blockIdx.x * blockDim.x + threadIdx.x;
    if (e < N_EDGES / 2) {
        int sh = (threadIdx.x & 1) * N_NODES;   // 2-way shard halves chains
        int2 d = __ldg(&dst2[e]);
        atomicAdd(&cnt[sh + d.x], 1);
        atomicAdd(&cnt[sh + d.y], 1);
    }
}

// Single-block scan; consumes both cnt shards and RE-ZEROES them.
__global__ __launch_bounds__(1024) void scan_kernel(
    int* __restrict__ cnt, int* __restrict__ rowptr,
    int* __restrict__ cursor, float* __restrict__ invdeg,
    float* __restrict__ stats)
{
    __shared__ int wsum[32];
    __shared__ int s_carry;
    const int t = threadIdx.x, lane = t & 31, w = t >> 5;
    if (t == 0) s_carry = 0;
    if (t < 512) stats[t] = 0.f;
    __syncthreads();

    const int CHUNK = 4096;
    for (int base = 0; base < N_NODES; base += CHUNK) {
        int i0 = base + t * 4;
        int v[4];
#pragma unroll
        for (int j = 0; j < 4; ++j) {
            int i = i0 + j;
            v[j] = (i < N_NODES) ? (cnt[i] + cnt[N_NODES + i]) : 0;
        }
        int tsum = v[0] + v[1] + v[2] + v[3];

        int x = tsum;
#pragma unroll
        for (int o = 1; o < 32; o <<= 1) {
            int y = __shfl_up_sync(~0u, x, o);
            if (lane >= o) x += y;
        }
        if (lane == 31) wsum[w] = x;
        __syncthreads();
        if (w == 0) {
            int s = wsum[lane];
#pragma unroll
            for (int o = 1; o < 32; o <<= 1) {
                int y = __shfl_up_sync(~0u, s, o);
                if (lane >= o) s += y;
            }
            wsum[lane] = s;
        }
        __syncthreads();
        int woff = (w == 0) ? 0 : wsum[w - 1];
        int run = s_carry + woff + (x - tsum);
#pragma unroll
        for (int j = 0; j < 4; ++j) {
            int i = i0 + j;
            if (i < N_NODES) {
                rowptr[i] = run;
                cursor[i] = run;
                invdeg[i] = 1.0f / fmaxf((float)v[j], 1.0f);
                cnt[i] = 0;                // restore zero for next launch
                cnt[N_NODES + i] = 0;
            }
            run += v[j];
        }
        __syncthreads();
        if (t == 1023) s_carry += wsum[31];
        __syncthreads();
    }
    if (t == 0) rowptr[N_NODES] = s_carry;
}

__global__ void fill_kernel(const int2* __restrict__ src2, const int2* __restrict__ dst2,
                            int* __restrict__ cursor, int* __restrict__ csrsrc) {
    int e = blockIdx.x * blockDim.x + threadIdx.x;
    if (e < N_EDGES / 2) {
        int2 s = __ldg(&src2[e]);
        int2 d = __ldg(&dst2[e]);
        int p0 = atomicAdd(&cursor[d.x], 1);
        int p1 = atomicAdd(&cursor[d.y], 1);
        csrsrc[p0] = s.x;
        csrsrc[p1] = s.y;
    }
}

// ===========================================================================
// helpers
// ===========================================================================
__device__ __forceinline__ uint32_t pkhf(float a, float b) {
    __half2 h = __float22half2_rn(make_float2(a, b));
    uint32_t r;
    memcpy(&r, &h, 4);
    return r;
}
__device__ __forceinline__ float2 hf2f(uint32_t u) {
    __half2 h;
    memcpy(&h, &u, 4);
    return __half22float2(h);
}
__device__ __forceinline__ float4 bn_relu4(float4 v, float4 sc, float4 sh) {
    v.x = fmaxf(fmaf(v.x, sc.x, sh.x), 0.f);
    v.y = fmaxf(fmaf(v.y, sc.y, sh.y), 0.f);
    v.z = fmaxf(fmaf(v.z, sc.z, sh.z), 0.f);
    v.w = fmaxf(fmaf(v.w, sc.w, sh.w), 0.f);
    return v;
}

// Splits 4 floats into f16 hi (packed pair) and scaled f16 residual.
__device__ __forceinline__ void split4(float4 v, uint32_t& hi0, uint32_t& hi1,
                                       uint32_t& lo0, uint32_t& lo1) {
    hi0 = pkhf(v.x, v.y);
    hi1 = pkhf(v.z, v.w);
    float2 f0 = hf2f(hi0), f1 = hf2f(hi1);
    lo0 = pkhf((v.x - f0.x) * LO_SCALE, (v.y - f0.y) * LO_SCALE);
    lo1 = pkhf((v.z - f1.x) * LO_SCALE, (v.w - f1.y) * LO_SCALE);
}

// Swizzled byte offset within a 128-row x 256B tile.
__device__ __forceinline__ uint32_t soff(int r, int byte) {
    return (uint32_t)(r * 256 + (byte ^ ((r & 7) << 4)));
}

// ===========================================================================
// prep: BN affine inline; emits f16 hi + scaled f16 lo images (8 floats/thr).
// Extra 16 blocks build the swizzled W^T hi/lo images (256B rows).
// ===========================================================================
__global__ __launch_bounds__(256) void prep_kernel(
    const float4* __restrict__ H,
    const float* __restrict__ stats,
    const float* __restrict__ gamma, const float* __restrict__ beta,
    int useAffine,
    uint4* __restrict__ xh16, uint4* __restrict__ xlo,
    const float* __restrict__ Ws, const float* __restrict__ Wn,
    uint4* __restrict__ whi, uint4* __restrict__ wlo)
{
    if (blockIdx.x >= PREP_BLOCKS) {
        int idx = (blockIdx.x - PREP_BLOCKS) * 256 + threadIdx.x;
        int pass = idx >> 11;
        int n = (idx >> 4) & 127;
        int ch = idx & 15;
        const float* W = pass ? Wn : Ws;
        float4 a, b;
        a.x = __ldg(&W[(ch * 8 + 0) * 128 + n]);
        a.y = __ldg(&W[(ch * 8 + 1) * 128 + n]);
        a.z = __ldg(&W[(ch * 8 + 2) * 128 + n]);
        a.w = __ldg(&W[(ch * 8 + 3) * 128 + n]);
        b.x = __ldg(&W[(ch * 8 + 4) * 128 + n]);
        b.y = __ldg(&W[(ch * 8 + 5) * 128 + n]);
        b.z = __ldg(&W[(ch * 8 + 6) * 128 + n]);
        b.w = __ldg(&W[(ch * 8 + 7) * 128 + n]);
        uint4 hi4, lo4;
        split4(a, hi4.x, hi4.y, lo4.x, lo4.y);
        split4(b, hi4.z, hi4.w, lo4.z, lo4.w);
        uint32_t off = (uint32_t)pass * 32768 + soff(n, ch * 16);
        *(uint4*)((char*)whi + off) = hi4;
        *(uint4*)((char*)wlo + off) = lo4;
        return;
    }

    __shared__ float s_aff[256];
    if (useAffine) {
        int t = threadIdx.x;
        if (t < 128) {
            const float invN = 1.0f / (float)N_NODES;
            float mu = __ldg(&stats[t]) * invN;
            float var = __ldg(&stats[128 + t]) * invN - mu * mu;
            float s = __ldg(&gamma[t]) * rsqrtf(var + EPS);
            s_aff[t] = s;
            s_aff[128 + t] = __ldg(&beta[t]) - mu * s;
        }
        __syncthreads();
    }

    int gid = blockIdx.x * blockDim.x + threadIdx.x;   // 0..N_NODES*16-1
    if (gid >= N_NODES * 16) return;
    int ch = gid & 15;
    float4 v0 = H[gid * 2];
    float4 v1 = H[gid * 2 + 1];
    if (useAffine) {
        float4 sc0 = ((const float4*)s_aff)[ch * 2];
        float4 sc1 = ((const float4*)s_aff)[ch * 2 + 1];
        float4 sh0 = ((const float4*)s_aff)[32 + ch * 2];
        float4 sh1 = ((const float4*)s_aff)[32 + ch * 2 + 1];
        v0 = bn_relu4(v0, sc0, sh0);
        v1 = bn_relu4(v1, sc1, sh1);
    }
    uint4 hi4, lo4;
    split4(v0, hi4.x, hi4.y, lo4.x, lo4.y);
    split4(v1, hi4.z, hi4.w, lo4.z, lo4.w);
    xh16[gid] = hi4;
    xlo[gid] = lo4;
}

// ===========================================================================
// Gather (warp per node, fp16 inputs, fp32 accumulate, scaled f16 split out)
// ===========================================================================
__global__ __launch_bounds__(256) void gather_kernel(
    const uint2* __restrict__ xh16,
    const int* __restrict__ rowptr,
    const int* __restrict__ csrsrc,
    const float* __restrict__ invdeg,
    uint2* __restrict__ agghi, uint2* __restrict__ agglo)
{
    int gid = blockIdx.x * blockDim.x + threadIdx.x;
    int node = gid >> 5;
    if (node >= N_NODES) return;
    int lane = gid & 31;

    int beg = __ldg(&rowptr[node]);
    int end = __ldg(&rowptr[node + 1]);
    float inv = __ldg(&invdeg[node]);

    float a0 = 0.f, a1 = 0.f, a2 = 0.f, a3 = 0.f;
    int p = beg;
    for (; p + 7 < end; p += 8) {
        uint2 d[8];
#pragma unroll
        for (int j = 0; j < 8; ++j) {
            int nb = __ldg(&csrsrc[p + j]);
            d[j] = __ldg(&xh16[nb * 32 + lane]);
        }
#pragma unroll
        for (int j = 0; j < 8; ++j) {
            float2 f0 = hf2f(d[j].x), f1 = hf2f(d[j].y);
            a0 += f0.x; a1 += f0.y; a2 += f1.x; a3 += f1.y;
        }
    }
    for (; p + 3 < end; p += 4) {
        uint2 d[4];
#pragma unroll
        for (int j = 0; j < 4; ++j) {
            int nb = __ldg(&csrsrc[p + j]);
            d[j] = __ldg(&xh16[nb * 32 + lane]);
        }
#pragma unroll
        for (int j = 0; j < 4; ++j) {
            float2 f0 = hf2f(d[j].x), f1 = hf2f(d[j].y);
            a0 += f0.x; a1 += f0.y; a2 += f1.x; a3 += f1.y;
        }
    }
    for (; p < end; ++p) {
        int nb = __ldg(&csrsrc[p]);
        uint2 d = __ldg(&xh16[nb * 32 + lane]);
        float2 f0 = hf2f(d.x), f1 = hf2f(d.y);
        a0 += f0.x; a1 += f0.y; a2 += f1.x; a3 += f1.y;
    }
    a0 *= inv; a1 *= inv; a2 *= inv; a3 *= inv;
    uint32_t h0 = pkhf(a0, a1), h1 = pkhf(a2, a3);
    float2 f0 = hf2f(h0), f1 = hf2f(h1);
    agghi[node * 32 + lane] = make_uint2(h0, h1);
    agglo[node * 32 + lane] = make_uint2(
        pkhf((a0 - f0.x) * LO_SCALE, (a1 - f0.y) * LO_SCALE),
        pkhf((a2 - f1.x) * LO_SCALE, (a3 - f1.y) * LO_SCALE));
}

// ===========================================================================
// mma.sync helpers
// ===========================================================================
__device__ __forceinline__ uint32_t smem_u32(const void* p) {
    uint32_t a;
    asm("{ .reg .u64 t; cvta.to.shared.u64 t, %1; cvt.u32.u64 %0, t; }"
        : "=r"(a) : "l"(p));
    return a;
}

__device__ __forceinline__ void ldsm4(uint32_t& r0, uint32_t& r1,
                                      uint32_t& r2, uint32_t& r3, uint32_t addr) {
    asm volatile("ldmatrix.sync.aligned.m8n8.x4.shared.b16 {%0,%1,%2,%3}, [%4];"
                 : "=r"(r0), "=r"(r1), "=r"(r2), "=r"(r3) : "r"(addr) : "memory");
}

__device__ __forceinline__ void mma16816(float* c, uint32_t a0, uint32_t a1,
                                         uint32_t a2, uint32_t a3,
                                         uint32_t b0, uint32_t b1) {
    asm volatile(
        "mma.sync.aligned.m16n8k16.row.col.f32.f16.f16.f32 "
        "{%0,%1,%2,%3}, {%4,%5,%6,%7}, {%8,%9}, {%0,%1,%2,%3};"
        : "+f"(c[0]), "+f"(c[1]), "+f"(c[2]), "+f"(c[3])
        : "r"(a0), "r"(a1), "r"(a2), "r"(a3), "r"(b0), "r"(b1));
}

// Pairwise named barrier: warps w and w+8 (64 threads), ids 1..8.
__device__ __forceinline__ void pair_bar(int pair) {
    asm volatile("bar.sync %0, 64;" :: "r"(pair + 1) : "memory");
}

// ===========================================================================
// Persistent fused SAGE layer GEMM: grid=148, all W images resident in SMEM.
// f16 hi/lo split with scaled-lo dual accumulators:
//   out = accH + accL/2048 + bias
// ===========================================================================
__global__ __launch_bounds__(512, 1) void sage_mma_kernel(
    const uint4* __restrict__ xhi4, const uint4* __restrict__ xlo4,
    const uint4* __restrict__ ahi4, const uint4* __restrict__ alo4,
    const uint4* __restrict__ wthi, const uint4* __restrict__ wtlo,
    const float* __restrict__ bias,
    float2* __restrict__ Out2,
    float* __restrict__ stats, int withBN)
{
    extern __shared__ char smem[];
    const uint32_t sbase = smem_u32(smem);
    const int tid = threadIdx.x;
    const int w = tid >> 5;
    const int lane = tid & 31;
    const int pairId = w & 7;
    const int m0 = pairId * 16;
    const int nhalf = w >> 3;

    float* s_sum = (float*)(smem + SM_STATS);
    float* s_sq = s_sum + 128;
    if (withBN && tid < 256) s_sum[tid] = 0.f;

    // ---- Load all four W images once (128 KB)
#pragma unroll
    for (int it = 0; it < 4; ++it) {
        int idx = tid + it * 512;
        ((uint4*)(smem + SM_W0HI))[idx] = __ldg(&wthi[idx]);
        ((uint4*)(smem + SM_W0LO))[idx] = __ldg(&wtlo[idx]);
        ((uint4*)(smem + SM_W1HI))[idx] = __ldg(&wthi[2048 + idx]);
        ((uint4*)(smem + SM_W1LO))[idx] = __ldg(&wtlo[2048 + idx]);
    }
    __syncthreads();

    const int aRow = m0 + (lane & 15);
    const uint32_t aBase = sbase + SM_XHI + (uint32_t)aRow * 256;
    const uint32_t aXor = (uint32_t)(aRow & 7) << 4;
    const uint32_t aSel = ((lane >> 4) & 1) * 16;
    const uint32_t bSel = ((lane >> 3) & 1) * 16;

    uint32_t bOff0[4], bXor[4];
#pragma unroll
    for (int ntp = 0; ntp < 4; ++ntp) {
        int bRow = nhalf * 64 + ntp * 16 + ((lane >> 4) & 1) * 8 + (lane & 7);
        bOff0[ntp] = sbase + SM_W0HI + (uint32_t)bRow * 256;
        bXor[ntp] = (uint32_t)(bRow & 7) << 4;
    }

    const uint32_t fillBase = (w < 8) ? SM_XHI : SM_XLO;

    for (int tile = blockIdx.x; tile < NTILES; tile += gridDim.x) {
        const int row0 = tile * TILE_M;

        float accH[8][4], accL[8][4];
#pragma unroll
        for (int nt = 0; nt < 8; ++nt)
#pragma unroll
            for (int q = 0; q < 4; ++q) { accH[nt][q] = 0.f; accL[nt][q] = 0.f; }

#pragma unroll
        for (int pass = 0; pass < 2; ++pass) {
            const uint4* Src = (w < 8)
                ? ((pass == 0) ? xhi4 : ahi4)
                : ((pass == 0) ? xlo4 : alo4);

            pair_bar(pairId);

            // ---- Fill this pair's 16 rows of one image (8 uint4 per lane)
#pragma unroll
            for (int i = 0; i < 8; ++i) {
                int idx = lane + i * 32;
                int ml = idx >> 4;
                int ch = idx & 15;
                int m = m0 + ml;
                int gr = row0 + m;
                uint4 v = make_uint4(0, 0, 0, 0);
                if (gr < N_NODES) v = __ldg(&Src[gr * 16 + ch]);
                *(uint4*)(smem + fillBase + soff(m, ch * 16)) = v;
            }

            pair_bar(pairId);

            const uint32_t wShift = (uint32_t)pass * 65536;

            // ---- MMA main loop
#pragma unroll
            for (int ks = 0; ks < 8; ++ks) {
                uint32_t aoff = ((uint32_t)(ks * 32) + aSel) ^ aXor;
                uint32_t ah0, ah1, ah2, ah3, al0, al1, al2, al3;
                ldsm4(ah0, ah1, ah2, ah3, aBase + aoff);
                ldsm4(al0, al1, al2, al3, aBase + 32768 + aoff);
#pragma unroll
                for (int ntp = 0; ntp < 4; ++ntp) {
                    uint32_t bb = bOff0[ntp] + wShift;
                    uint32_t boff = ((uint32_t)(ks * 32) + bSel) ^ bXor[ntp];
                    uint32_t bh0, bh1, bh2, bh3, bl0, bl1, bl2, bl3;
                    ldsm4(bh0, bh1, bh2, bh3, bb + boff);
                    ldsm4(bl0, bl1, bl2, bl3, bb + 32768 + boff);
                    mma16816(accH[2 * ntp], ah0, ah1, ah2, ah3, bh0, bh1);
                    mma16816(accL[2 * ntp], ah0, ah1, ah2, ah3, bl0, bl1);
                    mma16816(accL[2 * ntp], al0, al1, al2, al3, bh0, bh1);
                    mma16816(accH[2 * ntp + 1], ah0, ah1, ah2, ah3, bh2, bh3);
                    mma16816(accL[2 * ntp + 1], ah0, ah1, ah2, ah3, bl2, bl3);
                    mma16816(accL[2 * ntp + 1], al0, al1, al2, al3, bh2, bh3);
                }
            }
        }

        // ---- Per-tile epilogue: combine, bias, store, BN stats
        {
            int g = lane >> 2;
            int i = lane & 3;
            int grA = row0 + m0 + g;
            int grB = grA + 8;
            bool vA = grA < N_NODES, vB = grB < N_NODES;
#pragma unroll
            for (int nt = 0; nt < 8; ++nt) {
                int col = nhalf * 64 + nt * 8 + 2 * i;
                float2 bv = __ldg(&((const float2*)bias)[col >> 1]);
                float hA0 = fmaf(accL[nt][0], LO_INV, accH[nt][0]) + bv.x;
                float hA1 = fmaf(accL[nt][1], LO_INV, accH[nt][1]) + bv.y;
                float hB0 = fmaf(accL[nt][2], LO_INV, accH[nt][2]) + bv.x;
                float hB1 = fmaf(accL[nt][3], LO_INV, accH[nt][3]) + bv.y;
                if (vA) Out2[(size_t)grA * 64 + (col >> 1)] = make_float2(hA0, hA1);
                if (vB) Out2[(size_t)grB * 64 + (col >> 1)] = make_float2(hB0, hB1);
                if (withBN) {
                    float s0 = (vA ? hA0 : 0.f) + (vB ? hB0 : 0.f);
                    float s1 = (vA ? hA1 : 0.f) + (vB ? hB1 : 0.f);
                    float q0 = (vA ? hA0 * hA0 : 0.f) + (vB ? hB0 * hB0 : 0.f);
                    float q1 = (vA ? hA1 * hA1 : 0.f) + (vB ? hB1 * hB1 : 0.f);
#pragma unroll
                    for (int off = 16; off >= 4; off >>= 1) {
                        s0 += __shfl_down_sync(~0u, s0, off);
                        s1 += __shfl_down_sync(~0u, s1, off);
                        q0 += __shfl_down_sync(~0u, q0, off);
                        q1 += __shfl_down_sync(~0u, q1, off);
                    }
                    if (lane < 4) {
                        atomicAdd(&s_sum[col], s0);
                        atomicAdd(&s_sum[col + 1], s1);
                        atomicAdd(&s_sq[col], q0);
                        atomicAdd(&s_sq[col + 1], q1);
                    }
                }
            }
        }
    }

    if (withBN) {
        __syncthreads();
        if (tid < 128) {
            atomicAdd(&stats[tid], s_sum[tid]);
            atomicAdd(&stats[128 + tid], s_sq[tid]);
        }
    }
}

// ===========================================================================
extern "C" void kernel_launch(void* const* d_in, const int* in_sizes, int n_in,
                              void* d_out, int out_size) {
    const float* x   = (const float*)d_in[0];
    const int*   src = (const int*)  d_in[1];
    const int*   dst = (const int*)  d_in[2];
    const float* Ws1 = (const float*)d_in[3];
    const float* Wn1 = (const float*)d_in[4];
    const float* b1  = (const float*)d_in[5];
    const float* ga1 = (const float*)d_in[6];
    const float* be1 = (const float*)d_in[7];
    const float* Ws2 = (const float*)d_in[8];
    const float* Wn2 = (const float*)d_in[9];
    const float* b2  = (const float*)d_in[10];
    const float* ga2 = (const float*)d_in[11];
    const float* be2 = (const float*)d_in[12];
    const float* Ws3 = (const float*)d_in[13];
    const float* Wn3 = (const float*)d_in[14];
    const float* b3  = (const float*)d_in[15];
    float* out = (float*)d_out;

    float *bufA, *bufB, *invdeg, *stats;
    int *rowptr, *cnt, *cursor, *csrsrc;
    uint4 *xh16, *xlo, *agghi, *agglo, *wthi, *wtlo;
    cudaGetSymbolAddress((void**)&bufA,   g_bufA);
    cudaGetSymbolAddress((void**)&bufB,   g_bufB);
    cudaGetSymbolAddress((void**)&xh16,   g_xh16);
    cudaGetSymbolAddress((void**)&xlo,    g_xlo);
    cudaGetSymbolAddress((void**)&agghi,  g_agghi);
    cudaGetSymbolAddress((void**)&agglo,  g_agglo);
    cudaGetSymbolAddress((void**)&rowptr, g_rowptr);
    cudaGetSymbolAddress((void**)&cnt,    g_cnt);
    cudaGetSymbolAddress((void**)&cursor, g_cursor);
    cudaGetSymbolAddress((void**)&csrsrc, g_csrsrc);
    cudaGetSymbolAddress((void**)&invdeg, g_invdeg);
    cudaGetSymbolAddress((void**)&stats,  g_stats);
    cudaGetSymbolAddress((void**)&wthi,   g_wthi);
    cudaGetSymbolAddress((void**)&wtlo,   g_wtlo);

    cudaFuncSetAttribute(sage_mma_kernel,
                         cudaFuncAttributeMaxDynamicSharedMemorySize, SM_TOTAL);

    const int gthr_blocks = (N_NODES * 32 + 255) / 256;

    // Build CSR: cnt shards are zero on entry (module-load init; scan re-zeroes).
    hist_kernel<<<(N_EDGES / 2 + 255) / 256, 256>>>((const int2*)dst, cnt);
    scan_kernel<<<1, 1024>>>(cnt, rowptr, cursor, invdeg, stats);
    fill_kernel<<<(N_EDGES / 2 + 255) / 256, 256>>>((const int2*)src, (const int2*)dst,
                                                    cursor, csrsrc);

    // Layer 1 (stats -> g_stats[0:256))
    prep_kernel<<<PREP_BLOCKS + 16, 256>>>((const float4*)x, nullptr, nullptr, nullptr, 0,
                                           xh16, xlo, Ws1, Wn1, wthi, wtlo);
    gather_kernel<<<gthr_blocks, 256>>>((const uint2*)xh16, rowptr, csrsrc, invdeg,
                                        (uint2*)agghi, (uint2*)agglo);
    sage_mma_kernel<<<MMA_GRID, 512, SM_TOTAL>>>(
        xh16, xlo, agghi, agglo, wthi, wtlo, b1, (float2*)bufA, stats, 1);

    // Layer 2 (affine from stats[0:256), stats -> g_stats[256:512))
    prep_kernel<<<PREP_BLOCKS + 16, 256>>>((const float4*)bufA, stats, ga1, be1, 1,
                                           xh16, xlo, Ws2, Wn2, wthi, wtlo);
    gather_kernel<<<gthr_blocks, 256>>>((const uint2*)xh16, rowptr, csrsrc, invdeg,
                                        (uint2*)agghi, (uint2*)agglo);
    sage_mma_kernel<<<MMA_GRID, 512, SM_TOTAL>>>(
        xh16, xlo, agghi, agglo, wthi, wtlo, b2, (float2*)bufB, stats + 256, 1);

    // Layer 3 (affine from stats[256:512), no BN)
    prep_kernel<<<PREP_BLOCKS + 16, 256>>>((const float4*)bufB, stats + 256, ga2, be2, 1,
                                           xh16, xlo, Ws3, Wn3, wthi, wtlo);
    gather_kernel<<<gthr_blocks, 256>>>((const uint2*)xh16, rowptr, csrsrc, invdeg,
                                        (uint2*)agghi, (uint2*)agglo);
    sage_mma_kernel<<<MMA_GRID, 512, SM_TOTAL>>>(
        xh16, xlo, agghi, agglo, wthi, wtlo, b3, (float2*)out, stats, 0);
}

// round 16
// speedup vs baseline: 1.0200x; 1.0200x over previous
#include <cuda_runtime.h>
#include <cuda_bf16.h>
#include <cuda_fp16.h>
#include <cstdint>
#include <cstring>

#define N_NODES 50000
#define N_EDGES 800000
#define EPS 1e-5f

#define TILE_M 128
#define NTILES ((N_NODES + TILE_M - 1) / TILE_M)   // 391
#define MMA_GRID 148
#define PREP_BLOCKS ((N_NODES * 16 + 255) / 256)   // 3125

// SMEM layout (bytes): X hi/lo + all four W images resident
#define SM_XHI   0
#define SM_XLO   32768
#define SM_W0HI  65536
#define SM_W0LO  98304
#define SM_W1HI  131072
#define SM_W1LO  163840
#define SM_STATS 196608
#define SM_TOTAL (196608 + 1024)

// Scratch (__device__ globals, allocation-free rule).
__device__ float g_bufA[N_NODES * 128];
__device__ float g_bufB[N_NODES * 128];
__device__ uint4 g_xh16[N_NODES * 16];  // f16 activations (gather + GEMM hi)
__device__ uint4 g_xlo[N_NODES * 16];   // f16 residual (unscaled, GEMM lo)
__device__ uint4 g_agghi[N_NODES * 16];
__device__ uint4 g_agglo[N_NODES * 16];
__device__ int   g_rowptr[N_NODES + 1];
__device__ int   g_cnt[2 * N_NODES];    // sharded histogram (self-cleaning)
__device__ int   g_cursor[N_NODES];
__device__ int   g_csrsrc[N_EDGES];
__device__ float g_invdeg[N_NODES];
__device__ float g_stats[512];          // [0:256) layer1, [256:512) layer2
__device__ uint4 g_wthi[2 * 2048];      // pass-major W^T f16 hi images
__device__ uint4 g_wtlo[2 * 2048];      // f16 residual (unscaled)

// ===========================================================================
// CSR build
// ===========================================================================
__global__ void hist_kernel(const int2* __restrict__ dst2, int* __restrict__ cnt) {
    int e = blockIdx.x * blockDim.x + threadIdx.x;
    if (e < N_EDGES / 2) {
        int sh = (threadIdx.x & 1) * N_NODES;   // 2-way shard halves chains
        int2 d = __ldg(&dst2[e]);
        atomicAdd(&cnt[sh + d.x], 1);
        atomicAdd(&cnt[sh + d.y], 1);
    }
}

// Single-block scan; consumes both cnt shards and RE-ZEROES them.
__global__ __launch_bounds__(1024) void scan_kernel(
    int* __restrict__ cnt, int* __restrict__ rowptr,
    int* __restrict__ cursor, float* __restrict__ invdeg,
    float* __restrict__ stats)
{
    __shared__ int wsum[32];
    __shared__ int s_carry;
    const int t = threadIdx.x, lane = t & 31, w = t >> 5;
    if (t == 0) s_carry = 0;
    if (t < 512) stats[t] = 0.f;
    __syncthreads();

    const int CHUNK = 4096;
    for (int base = 0; base < N_NODES; base += CHUNK) {
        int i0 = base + t * 4;
        int v[4];
#pragma unroll
        for (int j = 0; j < 4; ++j) {
            int i = i0 + j;
            v[j] = (i < N_NODES) ? (cnt[i] + cnt[N_NODES + i]) : 0;
        }
        int tsum = v[0] + v[1] + v[2] + v[3];

        int x = tsum;
#pragma unroll
        for (int o = 1; o < 32; o <<= 1) {
            int y = __shfl_up_sync(~0u, x, o);
            if (lane >= o) x += y;
        }
        if (lane == 31) wsum[w] = x;
        __syncthreads();
        if (w == 0) {
            int s = wsum[lane];
#pragma unroll
            for (int o = 1; o < 32; o <<= 1) {
                int y = __shfl_up_sync(~0u, s, o);
                if (lane >= o) s += y;
            }
            wsum[lane] = s;
        }
        __syncthreads();
        int woff = (w == 0) ? 0 : wsum[w - 1];
        int run = s_carry + woff + (x - tsum);
#pragma unroll
        for (int j = 0; j < 4; ++j) {
            int i = i0 + j;
            if (i < N_NODES) {
                rowptr[i] = run;
                cursor[i] = run;
                invdeg[i] = 1.0f / fmaxf((float)v[j], 1.0f);
                cnt[i] = 0;
                cnt[N_NODES + i] = 0;
            }
            run += v[j];
        }
        __syncthreads();
        if (t == 1023) s_carry += wsum[31];
        __syncthreads();
    }
    if (t == 0) rowptr[N_NODES] = s_carry;
}

__global__ void fill_kernel(const int2* __restrict__ src2, const int2* __restrict__ dst2,
                            int* __restrict__ cursor, int* __restrict__ csrsrc) {
    int e = blockIdx.x * blockDim.x + threadIdx.x;
    if (e < N_EDGES / 2) {
        int2 s = __ldg(&src2[e]);
        int2 d = __ldg(&dst2[e]);
        int p0 = atomicAdd(&cursor[d.x], 1);
        int p1 = atomicAdd(&cursor[d.y], 1);
        csrsrc[p0] = s.x;
        csrsrc[p1] = s.y;
    }
}

// ===========================================================================
// helpers
// ===========================================================================
__device__ __forceinline__ uint32_t pkhf(float a, float b) {
    __half2 h = __float22half2_rn(make_float2(a, b));
    uint32_t r;
    memcpy(&r, &h, 4);
    return r;
}
__device__ __forceinline__ float2 hf2f(uint32_t u) {
    __half2 h;
    memcpy(&h, &u, 4);
    return __half22float2(h);
}
__device__ __forceinline__ float4 bn_relu4(float4 v, float4 sc, float4 sh) {
    v.x = fmaxf(fmaf(v.x, sc.x, sh.x), 0.f);
    v.y = fmaxf(fmaf(v.y, sc.y, sh.y), 0.f);
    v.z = fmaxf(fmaf(v.z, sc.z, sh.z), 0.f);
    v.w = fmaxf(fmaf(v.w, sc.w, sh.w), 0.f);
    return v;
}

// Splits 4 floats into f16 hi (packed pair) and f16 residual (unscaled).
__device__ __forceinline__ void split4(float4 v, uint32_t& hi0, uint32_t& hi1,
                                       uint32_t& lo0, uint32_t& lo1) {
    hi0 = pkhf(v.x, v.y);
    hi1 = pkhf(v.z, v.w);
    float2 f0 = hf2f(hi0), f1 = hf2f(hi1);
    lo0 = pkhf(v.x - f0.x, v.y - f0.y);
    lo1 = pkhf(v.z - f1.x, v.w - f1.y);
}

// Swizzled byte offset within a 128-row x 256B tile.
__device__ __forceinline__ uint32_t soff(int r, int byte) {
    return (uint32_t)(r * 256 + (byte ^ ((r & 7) << 4)));
}

// ===========================================================================
// prep: BN affine inline; emits f16 hi + f16 lo images (8 floats/thread).
// Extra 16 blocks build the swizzled W^T hi/lo images (256B rows).
// ===========================================================================
__global__ __launch_bounds__(256) void prep_kernel(
    const float4* __restrict__ H,
    const float* __restrict__ stats,
    const float* __restrict__ gamma, const float* __restrict__ beta,
    int useAffine,
    uint4* __restrict__ xh16, uint4* __restrict__ xlo,
    const float* __restrict__ Ws, const float* __restrict__ Wn,
    uint4* __restrict__ whi, uint4* __restrict__ wlo)
{
    if (blockIdx.x >= PREP_BLOCKS) {
        int idx = (blockIdx.x - PREP_BLOCKS) * 256 + threadIdx.x;
        int pass = idx >> 11;
        int n = (idx >> 4) & 127;
        int ch = idx & 15;
        const float* W = pass ? Wn : Ws;
        float4 a, b;
        a.x = __ldg(&W[(ch * 8 + 0) * 128 + n]);
        a.y = __ldg(&W[(ch * 8 + 1) * 128 + n]);
        a.z = __ldg(&W[(ch * 8 + 2) * 128 + n]);
        a.w = __ldg(&W[(ch * 8 + 3) * 128 + n]);
        b.x = __ldg(&W[(ch * 8 + 4) * 128 + n]);
        b.y = __ldg(&W[(ch * 8 + 5) * 128 + n]);
        b.z = __ldg(&W[(ch * 8 + 6) * 128 + n]);
        b.w = __ldg(&W[(ch * 8 + 7) * 128 + n]);
        uint4 hi4, lo4;
        split4(a, hi4.x, hi4.y, lo4.x, lo4.y);
        split4(b, hi4.z, hi4.w, lo4.z, lo4.w);
        uint32_t off = (uint32_t)pass * 32768 + soff(n, ch * 16);
        *(uint4*)((char*)whi + off) = hi4;
        *(uint4*)((char*)wlo + off) = lo4;
        return;
    }

    __shared__ float s_aff[256];
    if (useAffine) {
        int t = threadIdx.x;
        if (t < 128) {
            const float invN = 1.0f / (float)N_NODES;
            float mu = __ldg(&stats[t]) * invN;
            float var = __ldg(&stats[128 + t]) * invN - mu * mu;
            float s = __ldg(&gamma[t]) * rsqrtf(var + EPS);
            s_aff[t] = s;
            s_aff[128 + t] = __ldg(&beta[t]) - mu * s;
        }
        __syncthreads();
    }

    int gid = blockIdx.x * blockDim.x + threadIdx.x;   // 0..N_NODES*16-1
    if (gid >= N_NODES * 16) return;
    int ch = gid & 15;
    float4 v0 = H[gid * 2];
    float4 v1 = H[gid * 2 + 1];
    if (useAffine) {
        float4 sc0 = ((const float4*)s_aff)[ch * 2];
        float4 sc1 = ((const float4*)s_aff)[ch * 2 + 1];
        float4 sh0 = ((const float4*)s_aff)[32 + ch * 2];
        float4 sh1 = ((const float4*)s_aff)[32 + ch * 2 + 1];
        v0 = bn_relu4(v0, sc0, sh0);
        v1 = bn_relu4(v1, sc1, sh1);
    }
    uint4 hi4, lo4;
    split4(v0, hi4.x, hi4.y, lo4.x, lo4.y);
    split4(v1, hi4.z, hi4.w, lo4.z, lo4.w);
    xh16[gid] = hi4;
    xlo[gid] = lo4;
}

// ===========================================================================
// Gather (warp per node, f16 inputs, fp32 accumulate, f16 split out)
// ===========================================================================
__global__ __launch_bounds__(256) void gather_kernel(
    const uint2* __restrict__ xh16,
    const int* __restrict__ rowptr,
    const int* __restrict__ csrsrc,
    const float* __restrict__ invdeg,
    uint2* __restrict__ agghi, uint2* __restrict__ agglo)
{
    int gid = blockIdx.x * blockDim.x + threadIdx.x;
    int node = gid >> 5;
    if (node >= N_NODES) return;
    int lane = gid & 31;

    int beg = __ldg(&rowptr[node]);
    int end = __ldg(&rowptr[node + 1]);
    float inv = __ldg(&invdeg[node]);

    float a0 = 0.f, a1 = 0.f, a2 = 0.f, a3 = 0.f;
    int p = beg;
    for (; p + 7 < end; p += 8) {
        uint2 d[8];
#pragma unroll
        for (int j = 0; j < 8; ++j) {
            int nb = __ldg(&csrsrc[p + j]);
            d[j] = __ldg(&xh16[nb * 32 + lane]);
        }
#pragma unroll
        for (int j = 0; j < 8; ++j) {
            float2 f0 = hf2f(d[j].x), f1 = hf2f(d[j].y);
            a0 += f0.x; a1 += f0.y; a2 += f1.x; a3 += f1.y;
        }
    }
    for (; p + 3 < end; p += 4) {
        uint2 d[4];
#pragma unroll
        for (int j = 0; j < 4; ++j) {
            int nb = __ldg(&csrsrc[p + j]);
            d[j] = __ldg(&xh16[nb * 32 + lane]);
        }
#pragma unroll
        for (int j = 0; j < 4; ++j) {
            float2 f0 = hf2f(d[j].x), f1 = hf2f(d[j].y);
            a0 += f0.x; a1 += f0.y; a2 += f1.x; a3 += f1.y;
        }
    }
    for (; p < end; ++p) {
        int nb = __ldg(&csrsrc[p]);
        uint2 d = __ldg(&xh16[nb * 32 + lane]);
        float2 f0 = hf2f(d.x), f1 = hf2f(d.y);
        a0 += f0.x; a1 += f0.y; a2 += f1.x; a3 += f1.y;
    }
    a0 *= inv; a1 *= inv; a2 *= inv; a3 *= inv;
    uint32_t h0 = pkhf(a0, a1), h1 = pkhf(a2, a3);
    float2 f0 = hf2f(h0), f1 = hf2f(h1);
    agghi[node * 32 + lane] = make_uint2(h0, h1);
    agglo[node * 32 + lane] = make_uint2(pkhf(a0 - f0.x, a1 - f0.y),
                                         pkhf(a2 - f1.x, a3 - f1.y));
}

// ===========================================================================
// mma.sync helpers
// ===========================================================================
__device__ __forceinline__ uint32_t smem_u32(const void* p) {
    uint32_t a;
    asm("{ .reg .u64 t; cvta.to.shared.u64 t, %1; cvt.u32.u64 %0, t; }"
        : "=r"(a) : "l"(p));
    return a;
}

__device__ __forceinline__ void ldsm4(uint32_t& r0, uint32_t& r1,
                                      uint32_t& r2, uint32_t& r3, uint32_t addr) {
    asm volatile("ldmatrix.sync.aligned.m8n8.x4.shared.b16 {%0,%1,%2,%3}, [%4];"
                 : "=r"(r0), "=r"(r1), "=r"(r2), "=r"(r3) : "r"(addr) : "memory");
}

__device__ __forceinline__ void mma16816(float* c, uint32_t a0, uint32_t a1,
                                         uint32_t a2, uint32_t a3,
                                         uint32_t b0, uint32_t b1) {
    asm volatile(
        "mma.sync.aligned.m16n8k16.row.col.f32.f16.f16.f32 "
        "{%0,%1,%2,%3}, {%4,%5,%6,%7}, {%8,%9}, {%0,%1,%2,%3};"
        : "+f"(c[0]), "+f"(c[1]), "+f"(c[2]), "+f"(c[3])
        : "r"(a0), "r"(a1), "r"(a2), "r"(a3), "r"(b0), "r"(b1));
}

// Pairwise named barrier: warps w and w+8 (64 threads), ids 1..8.
__device__ __forceinline__ void pair_bar(int pair) {
    asm volatile("bar.sync %0, 64;" :: "r"(pair + 1) : "memory");
}

// ===========================================================================
// Persistent fused SAGE layer GEMM: grid=148, all W images resident in SMEM.
// f16 hi/lo 3-term split, SINGLE fp32 accumulator (32 regs):
//   acc += Ahi*Bhi + Ahi*Blo + Alo*Bhi
// ===========================================================================
__global__ __launch_bounds__(512, 1) void sage_mma_kernel(
    const uint4* __restrict__ xhi4, const uint4* __restrict__ xlo4,
    const uint4* __restrict__ ahi4, const uint4* __restrict__ alo4,
    const uint4* __restrict__ wthi, const uint4* __restrict__ wtlo,
    const float* __restrict__ bias,
    float2* __restrict__ Out2,
    float* __restrict__ stats, int withBN)
{
    extern __shared__ char smem[];
    const uint32_t sbase = smem_u32(smem);
    const int tid = threadIdx.x;
    const int w = tid >> 5;
    const int lane = tid & 31;
    const int pairId = w & 7;
    const int m0 = pairId * 16;
    const int nhalf = w >> 3;

    float* s_sum = (float*)(smem + SM_STATS);
    float* s_sq = s_sum + 128;
    if (withBN && tid < 256) s_sum[tid] = 0.f;

    // ---- Load all four W images once (128 KB)
#pragma unroll
    for (int it = 0; it < 4; ++it) {
        int idx = tid + it * 512;
        ((uint4*)(smem + SM_W0HI))[idx] = __ldg(&wthi[idx]);
        ((uint4*)(smem + SM_W0LO))[idx] = __ldg(&wtlo[idx]);
        ((uint4*)(smem + SM_W1HI))[idx] = __ldg(&wthi[2048 + idx]);
        ((uint4*)(smem + SM_W1LO))[idx] = __ldg(&wtlo[2048 + idx]);
    }
    __syncthreads();

    const int aRow = m0 + (lane & 15);
    const uint32_t aBase = sbase + SM_XHI + (uint32_t)aRow * 256;
    const uint32_t aXor = (uint32_t)(aRow & 7) << 4;
    const uint32_t aSel = ((lane >> 4) & 1) * 16;
    const uint32_t bSel = ((lane >> 3) & 1) * 16;

    uint32_t bOff0[4], bXor[4];
#pragma unroll
    for (int ntp = 0; ntp < 4; ++ntp) {
        int bRow = nhalf * 64 + ntp * 16 + ((lane >> 4) & 1) * 8 + (lane & 7);
        bOff0[ntp] = sbase + SM_W0HI + (uint32_t)bRow * 256;
        bXor[ntp] = (uint32_t)(bRow & 7) << 4;
    }

    const uint32_t fillBase = (w < 8) ? SM_XHI : SM_XLO;

    for (int tile = blockIdx.x; tile < NTILES; tile += gridDim.x) {
        const int row0 = tile * TILE_M;

        float acc[8][4];
#pragma unroll
        for (int nt = 0; nt < 8; ++nt)
#pragma unroll
            for (int q = 0; q < 4; ++q) acc[nt][q] = 0.f;

#pragma unroll
        for (int pass = 0; pass < 2; ++pass) {
            const uint4* Src = (w < 8)
                ? ((pass == 0) ? xhi4 : ahi4)
                : ((pass == 0) ? xlo4 : alo4);

            pair_bar(pairId);

            // ---- Fill this pair's 16 rows of one image (8 uint4 per lane)
#pragma unroll
            for (int i = 0; i < 8; ++i) {
                int idx = lane + i * 32;
                int ml = idx >> 4;
                int ch = idx & 15;
                int m = m0 + ml;
                int gr = row0 + m;
                uint4 v = make_uint4(0, 0, 0, 0);
                if (gr < N_NODES) v = __ldg(&Src[gr * 16 + ch]);
                *(uint4*)(smem + fillBase + soff(m, ch * 16)) = v;
            }

            pair_bar(pairId);

            const uint32_t wShift = (uint32_t)pass * 65536;

            // ---- MMA main loop
#pragma unroll
            for (int ks = 0; ks < 8; ++ks) {
                uint32_t aoff = ((uint32_t)(ks * 32) + aSel) ^ aXor;
                uint32_t ah0, ah1, ah2, ah3, al0, al1, al2, al3;
                ldsm4(ah0, ah1, ah2, ah3, aBase + aoff);
                ldsm4(al0, al1, al2, al3, aBase + 32768 + aoff);
#pragma unroll
                for (int ntp = 0; ntp < 4; ++ntp) {
                    uint32_t bb = bOff0[ntp] + wShift;
                    uint32_t boff = ((uint32_t)(ks * 32) + bSel) ^ bXor[ntp];
                    uint32_t bh0, bh1, bh2, bh3, bl0, bl1, bl2, bl3;
                    ldsm4(bh0, bh1, bh2, bh3, bb + boff);
                    ldsm4(bl0, bl1, bl2, bl3, bb + 32768 + boff);
                    mma16816(acc[2 * ntp], ah0, ah1, ah2, ah3, bh0, bh1);
                    mma16816(acc[2 * ntp], ah0, ah1, ah2, ah3, bl0, bl1);
                    mma16816(acc[2 * ntp], al0, al1, al2, al3, bh0, bh1);
                    mma16816(acc[2 * ntp + 1], ah0, ah1, ah2, ah3, bh2, bh3);
                    mma16816(acc[2 * ntp + 1], ah0, ah1, ah2, ah3, bl2, bl3);
                    mma16816(acc[2 * ntp + 1], al0, al1, al2, al3, bh2, bh3);
                }
            }
        }

        // ---- Per-tile epilogue: bias + store + BN stats
        {
            int g = lane >> 2;
            int i = lane & 3;
            int grA = row0 + m0 + g;
            int grB = grA + 8;
            bool vA = grA < N_NODES, vB = grB < N_NODES;
#pragma unroll
            for (int nt = 0; nt < 8; ++nt) {
                int col = nhalf * 64 + nt * 8 + 2 * i;
                float2 bv = __ldg(&((const float2*)bias)[col >> 1]);
                float hA0 = acc[nt][0] + bv.x, hA1 = acc[nt][1] + bv.y;
                float hB0 = acc[nt][2] + bv.x, hB1 = acc[nt][3] + bv.y;
                if (vA) Out2[(size_t)grA * 64 + (col >> 1)] = make_float2(hA0, hA1);
                if (vB) Out2[(size_t)grB * 64 + (col >> 1)] = make_float2(hB0, hB1);
                if (withBN) {
                    float s0 = (vA ? hA0 : 0.f) + (vB ? hB0 : 0.f);
                    float s1 = (vA ? hA1 : 0.f) + (vB ? hB1 : 0.f);
                    float q0 = (vA ? hA0 * hA0 : 0.f) + (vB ? hB0 * hB0 : 0.f);
                    float q1 = (vA ? hA1 * hA1 : 0.f) + (vB ? hB1 * hB1 : 0.f);
#pragma unroll
                    for (int off = 16; off >= 4; off >>= 1) {
                        s0 += __shfl_down_sync(~0u, s0, off);
                        s1 += __shfl_down_sync(~0u, s1, off);
                        q0 += __shfl_down_sync(~0u, q0, off);
                        q1 += __shfl_down_sync(~0u, q1, off);
                    }
                    if (lane < 4) {
                        atomicAdd(&s_sum[col], s0);
                        atomicAdd(&s_sum[col + 1], s1);
                        atomicAdd(&s_sq[col], q0);
                        atomicAdd(&s_sq[col + 1], q1);
                    }
                }
            }
        }
    }

    if (withBN) {
        __syncthreads();
        if (tid < 128) {
            atomicAdd(&stats[tid], s_sum[tid]);
            atomicAdd(&stats[128 + tid], s_sq[tid]);
        }
    }
}

// ===========================================================================
extern "C" void kernel_launch(void* const* d_in, const int* in_sizes, int n_in,
                              void* d_out, int out_size) {
    const float* x   = (const float*)d_in[0];
    const int*   src = (const int*)  d_in[1];
    const int*   dst = (const int*)  d_in[2];
    const float* Ws1 = (const float*)d_in[3];
    const float* Wn1 = (const float*)d_in[4];
    const float* b1  = (const float*)d_in[5];
    const float* ga1 = (const float*)d_in[6];
    const float* be1 = (const float*)d_in[7];
    const float* Ws2 = (const float*)d_in[8];
    const float* Wn2 = (const float*)d_in[9];
    const float* b2  = (const float*)d_in[10];
    const float* ga2 = (const float*)d_in[11];
    const float* be2 = (const float*)d_in[12];
    const float* Ws3 = (const float*)d_in[13];
    const float* Wn3 = (const float*)d_in[14];
    const float* b3  = (const float*)d_in[15];
    float* out = (float*)d_out;

    float *bufA, *bufB, *invdeg, *stats;
    int *rowptr, *cnt, *cursor, *csrsrc;
    uint4 *xh16, *xlo, *agghi, *agglo, *wthi, *wtlo;
    cudaGetSymbolAddress((void**)&bufA,   g_bufA);
    cudaGetSymbolAddress((void**)&bufB,   g_bufB);
    cudaGetSymbolAddress((void**)&xh16,   g_xh16);
    cudaGetSymbolAddress((void**)&xlo,    g_xlo);
    cudaGetSymbolAddress((void**)&agghi,  g_agghi);
    cudaGetSymbolAddress((void**)&agglo,  g_agglo);
    cudaGetSymbolAddress((void**)&rowptr, g_rowptr);
    cudaGetSymbolAddress((void**)&cnt,    g_cnt);
    cudaGetSymbolAddress((void**)&cursor, g_cursor);
    cudaGetSymbolAddress((void**)&csrsrc, g_csrsrc);
    cudaGetSymbolAddress((void**)&invdeg, g_invdeg);
    cudaGetSymbolAddress((void**)&stats,  g_stats);
    cudaGetSymbolAddress((void**)&wthi,   g_wthi);
    cudaGetSymbolAddress((void**)&wtlo,   g_wtlo);

    cudaFuncSetAttribute(sage_mma_kernel,
                         cudaFuncAttributeMaxDynamicSharedMemorySize, SM_TOTAL);

    const int gthr_blocks = (N_NODES * 32 + 255) / 256;

    // Build CSR: cnt shards are zero on entry (module-load init; scan re-zeroes).
    hist_kernel<<<(N_EDGES / 2 + 255) / 256, 256>>>((const int2*)dst, cnt);
    scan_kernel<<<1, 1024>>>(cnt, rowptr, cursor, invdeg, stats);
    fill_kernel<<<(N_EDGES / 2 + 255) / 256, 256>>>((const int2*)src, (const int2*)dst,
                                                    cursor, csrsrc);

    // Layer 1 (stats -> g_stats[0:256))
    prep_kernel<<<PREP_BLOCKS + 16, 256>>>((const float4*)x, nullptr, nullptr, nullptr, 0,
                                           xh16, xlo, Ws1, Wn1, wthi, wtlo);
    gather_kernel<<<gthr_blocks, 256>>>((const uint2*)xh16, rowptr, csrsrc, invdeg,
                                        (uint2*)agghi, (uint2*)agglo);
    sage_mma_kernel<<<MMA_GRID, 512, SM_TOTAL>>>(
        xh16, xlo, agghi, agglo, wthi, wtlo, b1, (float2*)bufA, stats, 1);

    // Layer 2 (affine from stats[0:256), stats -> g_stats[256:512))
    prep_kernel<<<PREP_BLOCKS + 16, 256>>>((const float4*)bufA, stats, ga1, be1, 1,
                                           xh16, xlo, Ws2, Wn2, wthi, wtlo);
    gather_kernel<<<gthr_blocks, 256>>>((const uint2*)xh16, rowptr, csrsrc, invdeg,
                                        (uint2*)agghi, (uint2*)agglo);
    sage_mma_kernel<<<MMA_GRID, 512, SM_TOTAL>>>(
        xh16, xlo, agghi, agglo, wthi, wtlo, b2, (float2*)bufB, stats + 256, 1);

    // Layer 3 (affine from stats[256:512), no BN)
    prep_kernel<<<PREP_BLOCKS + 16, 256>>>((const float4*)bufB, stats + 256, ga2, be2, 1,
                                           xh16, xlo, Ws3, Wn3, wthi, wtlo);
    gather_kernel<<<gthr_blocks, 256>>>((const uint2*)xh16, rowptr, csrsrc, invdeg,
                                        (uint2*)agghi, (uint2*)agglo);
    sage_mma_kernel<<<MMA_GRID, 512, SM_TOTAL>>>(
        xh16, xlo, agghi, agglo, wthi, wtlo, b3, (float2*)out, stats, 0);
}

// round 17
// speedup vs baseline: 1.0800x; 1.0588x over previous
#include <cuda_runtime.h>
#include <cuda_bf16.h>
#include <cuda_fp16.h>
#include <cstdint>
#include <cstring>

#define N_NODES 50000
#define N_EDGES 800000
#define EPS 1e-5f

#define TILE_M 128
#define NTILES ((N_NODES + TILE_M - 1) / TILE_M)   // 391
#define MMA_GRID 148
#define PREP_BLOCKS ((N_NODES * 32 + 255) / 256)

// SMEM layout (bytes): X hi/lo + all four W images resident
#define SM_XHI   0
#define SM_XLO   32768
#define SM_W0HI  65536
#define SM_W0LO  98304
#define SM_W1HI  131072
#define SM_W1LO  163840
#define SM_STATS 196608
#define SM_TOTAL (196608 + 1024)

// Scratch (__device__ globals, allocation-free rule)
__device__ float g_bufA[N_NODES * 128];
__device__ float g_bufB[N_NODES * 128];
__device__ uint4 g_xhi[N_NODES * 16];   // bf16 hi activations (GEMM)
__device__ uint4 g_xlo[N_NODES * 16];   // bf16 lo activations (GEMM)
__device__ uint4 g_xh16[N_NODES * 16];  // fp16 activations (gather)
__device__ uint4 g_agghi[N_NODES * 16];
__device__ uint4 g_agglo[N_NODES * 16];
__device__ int   g_rowptr[N_NODES + 1];
__device__ int   g_cursor[N_NODES];
__device__ int   g_csrsrc[N_EDGES];
__device__ float g_invdeg[N_NODES];
__device__ float g_stats[512];          // [0:256) layer1, [256:512) layer2
__device__ uint4 g_wthi[2 * 2048];      // pass-major W^T hi images (32KB each)
__device__ uint4 g_wtlo[2 * 2048];

// ===========================================================================
// CSR build (verbatim round-11 scheme: zero + int4 hist/fill + const scan)
// ===========================================================================
__global__ void zero_int_kernel(int4* __restrict__ p, int n4) {
    int i = blockIdx.x * blockDim.x + threadIdx.x;
    if (i < n4) p[i] = make_int4(0, 0, 0, 0);
}

__global__ void hist_kernel(const int4* __restrict__ dst4, int* __restrict__ cnt) {
    int e = blockIdx.x * blockDim.x + threadIdx.x;
    if (e < N_EDGES / 4) {
        int4 d = __ldg(&dst4[e]);
        atomicAdd(&cnt[d.x], 1);
        atomicAdd(&cnt[d.y], 1);
        atomicAdd(&cnt[d.z], 1);
        atomicAdd(&cnt[d.w], 1);
    }
}

__global__ __launch_bounds__(1024) void scan_kernel(
    const int* __restrict__ cnt_in, int* __restrict__ rowptr,
    int* __restrict__ cursor, float* __restrict__ invdeg,
    float* __restrict__ stats)
{
    __shared__ int wsum[32];
    __shared__ int s_carry;
    const int t = threadIdx.x, lane = t & 31, w = t >> 5;
    if (t == 0) s_carry = 0;
    if (t < 512) stats[t] = 0.f;
    __syncthreads();

    const int CHUNK = 4096;
    for (int base = 0; base < N_NODES; base += CHUNK) {
        int i0 = base + t * 4;
        int v[4];
#pragma unroll
        for (int j = 0; j < 4; ++j)
            v[j] = (i0 + j < N_NODES) ? cnt_in[i0 + j] : 0;
        int tsum = v[0] + v[1] + v[2] + v[3];

        int x = tsum;
#pragma unroll
        for (int o = 1; o < 32; o <<= 1) {
            int y = __shfl_up_sync(~0u, x, o);
            if (lane >= o) x += y;
        }
        if (lane == 31) wsum[w] = x;
        __syncthreads();
        if (w == 0) {
            int s = wsum[lane];
#pragma unroll
            for (int o = 1; o < 32; o <<= 1) {
                int y = __shfl_up_sync(~0u, s, o);
                if (lane >= o) s += y;
            }
            wsum[lane] = s;
        }
        __syncthreads();
        int woff = (w == 0) ? 0 : wsum[w - 1];
        int run = s_carry + woff + (x - tsum);
#pragma unroll
        for (int j = 0; j < 4; ++j) {
            int i = i0 + j;
            if (i < N_NODES) {
                rowptr[i] = run;
                cursor[i] = run;
                invdeg[i] = 1.0f / fmaxf((float)v[j], 1.0f);
            }
            run += v[j];
        }
        __syncthreads();
        if (t == 1023) s_carry += wsum[31];
        __syncthreads();
    }
    if (t == 0) rowptr[N_NODES] = s_carry;
}

__global__ void fill_kernel(const int4* __restrict__ src4, const int4* __restrict__ dst4,
                            int* __restrict__ cursor, int* __restrict__ csrsrc) {
    int e = blockIdx.x * blockDim.x + threadIdx.x;
    if (e < N_EDGES / 4) {
        int4 s = __ldg(&src4[e]);
        int4 d = __ldg(&dst4[e]);
        int p0 = atomicAdd(&cursor[d.x], 1);
        int p1 = atomicAdd(&cursor[d.y], 1);
        int p2 = atomicAdd(&cursor[d.z], 1);
        int p3 = atomicAdd(&cursor[d.w], 1);
        csrsrc[p0] = s.x;
        csrsrc[p1] = s.y;
        csrsrc[p2] = s.z;
        csrsrc[p3] = s.w;
    }
}

// ===========================================================================
// helpers
// ===========================================================================
__device__ __forceinline__ uint32_t pkbf(float a, float b) {
    __nv_bfloat162 h = __float22bfloat162_rn(make_float2(a, b));
    uint32_t r;
    memcpy(&r, &h, 4);
    return r;
}
__device__ __forceinline__ uint32_t pkhf(float a, float b) {
    __half2 h = __float22half2_rn(make_float2(a, b));
    uint32_t r;
    memcpy(&r, &h, 4);
    return r;
}
__device__ __forceinline__ float bfhi(float a) {
    return __bfloat162float(__float2bfloat16_rn(a));
}
__device__ __forceinline__ float2 hf2f(uint32_t u) {
    __half2 h;
    memcpy(&h, &u, 4);
    return __half22float2(h);
}
__device__ __forceinline__ float4 bn_relu4(float4 v, float4 sc, float4 sh) {
    v.x = fmaxf(fmaf(v.x, sc.x, sh.x), 0.f);
    v.y = fmaxf(fmaf(v.y, sc.y, sh.y), 0.f);
    v.z = fmaxf(fmaf(v.z, sc.z, sh.z), 0.f);
    v.w = fmaxf(fmaf(v.w, sc.w, sh.w), 0.f);
    return v;
}

// Swizzled byte offset within a 128-row x 256B tile.
__device__ __forceinline__ uint32_t soff(int r, int byte) {
    return (uint32_t)(r * 256 + (byte ^ ((r & 7) << 4)));
}

// ===========================================================================
// prep: BN affine computed inline from stats; emits split-bf16 + fp16 images.
// Extra 16 blocks build the swizzled W^T hi/lo images (256B rows).
// ===========================================================================
__global__ __launch_bounds__(256) void prep_kernel(
    const float4* __restrict__ H,
    const float* __restrict__ stats,
    const float* __restrict__ gamma, const float* __restrict__ beta,
    int useAffine,
    uint2* __restrict__ xhi, uint2* __restrict__ xlo, uint2* __restrict__ xh16,
    const float* __restrict__ Ws, const float* __restrict__ Wn,
    uint4* __restrict__ whi, uint4* __restrict__ wlo)
{
    if (blockIdx.x >= PREP_BLOCKS) {
        int idx = (blockIdx.x - PREP_BLOCKS) * 256 + threadIdx.x;
        int pass = idx >> 11;
        int n = (idx >> 4) & 127;
        int ch = idx & 15;
        const float* W = pass ? Wn : Ws;
        float v[8], h[8];
#pragma unroll
        for (int j = 0; j < 8; ++j) {
            v[j] = __ldg(&W[(ch * 8 + j) * 128 + n]);
            h[j] = bfhi(v[j]);
        }
        uint4 hi4, lo4;
        hi4.x = pkbf(h[0], h[1]); hi4.y = pkbf(h[2], h[3]);
        hi4.z = pkbf(h[4], h[5]); hi4.w = pkbf(h[6], h[7]);
        lo4.x = pkbf(v[0] - h[0], v[1] - h[1]);
        lo4.y = pkbf(v[2] - h[2], v[3] - h[3]);
        lo4.z = pkbf(v[4] - h[4], v[5] - h[5]);
        lo4.w = pkbf(v[6] - h[6], v[7] - h[7]);
        uint32_t off = (uint32_t)pass * 32768 + soff(n, ch * 16);
        *(uint4*)((char*)whi + off) = hi4;
        *(uint4*)((char*)wlo + off) = lo4;
        return;
    }

    __shared__ float s_aff[256];
    if (useAffine) {
        int t = threadIdx.x;
        if (t < 128) {
            const float invN = 1.0f / (float)N_NODES;
            float mu = __ldg(&stats[t]) * invN;
            float var = __ldg(&stats[128 + t]) * invN - mu * mu;
            float s = __ldg(&gamma[t]) * rsqrtf(var + EPS);
            s_aff[t] = s;
            s_aff[128 + t] = __ldg(&beta[t]) - mu * s;
        }
        __syncthreads();
    }

    int gid = blockIdx.x * blockDim.x + threadIdx.x;
    if (gid >= N_NODES * 32) return;
    float4 v = H[gid];
    if (useAffine) {
        int c = gid & 31;
        float4 sc = ((const float4*)s_aff)[c];
        float4 sh = ((const float4*)s_aff)[32 + c];
        v = bn_relu4(v, sc, sh);
    }
    float h0 = bfhi(v.x), h1 = bfhi(v.y), h2 = bfhi(v.z), h3 = bfhi(v.w);
    xhi[gid] = make_uint2(pkbf(h0, h1), pkbf(h2, h3));
    xlo[gid] = make_uint2(pkbf(v.x - h0, v.y - h1), pkbf(v.z - h2, v.w - h3));
    xh16[gid] = make_uint2(pkhf(v.x, v.y), pkhf(v.z, v.w));
}

// ===========================================================================
// Gather (warp per node, fp16 inputs, fp32 accumulate, split-bf16 output)
// ===========================================================================
__global__ __launch_bounds__(256) void gather_kernel(
    const uint2* __restrict__ xh16,
    const int* __restrict__ rowptr,
    const int* __restrict__ csrsrc,
    const float* __restrict__ invdeg,
    uint2* __restrict__ agghi, uint2* __restrict__ agglo)
{
    int gid = blockIdx.x * blockDim.x + threadIdx.x;
    int node = gid >> 5;
    if (node >= N_NODES) return;
    int lane = gid & 31;

    int beg = __ldg(&rowptr[node]);
    int end = __ldg(&rowptr[node + 1]);
    float inv = __ldg(&invdeg[node]);

    float a0 = 0.f, a1 = 0.f, a2 = 0.f, a3 = 0.f;
    int p = beg;
    for (; p + 7 < end; p += 8) {
        uint2 d[8];
#pragma unroll
        for (int j = 0; j < 8; ++j) {
            int nb = __ldg(&csrsrc[p + j]);
            d[j] = __ldg(&xh16[nb * 32 + lane]);
        }
#pragma unroll
        for (int j = 0; j < 8; ++j) {
            float2 f0 = hf2f(d[j].x), f1 = hf2f(d[j].y);
            a0 += f0.x; a1 += f0.y; a2 += f1.x; a3 += f1.y;
        }
    }
    for (; p + 3 < end; p += 4) {
        uint2 d[4];
#pragma unroll
        for (int j = 0; j < 4; ++j) {
            int nb = __ldg(&csrsrc[p + j]);
            d[j] = __ldg(&xh16[nb * 32 + lane]);
        }
#pragma unroll
        for (int j = 0; j < 4; ++j) {
            float2 f0 = hf2f(d[j].x), f1 = hf2f(d[j].y);
            a0 += f0.x; a1 += f0.y; a2 += f1.x; a3 += f1.y;
        }
    }
    for (; p < end; ++p) {
        int nb = __ldg(&csrsrc[p]);
        uint2 d = __ldg(&xh16[nb * 32 + lane]);
        float2 f0 = hf2f(d.x), f1 = hf2f(d.y);
        a0 += f0.x; a1 += f0.y; a2 += f1.x; a3 += f1.y;
    }
    a0 *= inv; a1 *= inv; a2 *= inv; a3 *= inv;
    float h0 = bfhi(a0), h1 = bfhi(a1), h2 = bfhi(a2), h3 = bfhi(a3);
    agghi[node * 32 + lane] = make_uint2(pkbf(h0, h1), pkbf(h2, h3));
    agglo[node * 32 + lane] = make_uint2(pkbf(a0 - h0, a1 - h1), pkbf(a2 - h2, a3 - h3));
}

// ===========================================================================
// mma.sync helpers
// ===========================================================================
__device__ __forceinline__ uint32_t smem_u32(const void* p) {
    uint32_t a;
    asm("{ .reg .u64 t; cvta.to.shared.u64 t, %1; cvt.u32.u64 %0, t; }"
        : "=r"(a) : "l"(p));
    return a;
}

__device__ __forceinline__ void ldsm4(uint32_t& r0, uint32_t& r1,
                                      uint32_t& r2, uint32_t& r3, uint32_t addr) {
    asm volatile("ldmatrix.sync.aligned.m8n8.x4.shared.b16 {%0,%1,%2,%3}, [%4];"
                 : "=r"(r0), "=r"(r1), "=r"(r2), "=r"(r3) : "r"(addr) : "memory");
}

__device__ __forceinline__ void mma16816(float* c, uint32_t a0, uint32_t a1,
                                         uint32_t a2, uint32_t a3,
                                         uint32_t b0, uint32_t b1) {
    asm volatile(
        "mma.sync.aligned.m16n8k16.row.col.f32.bf16.bf16.f32 "
        "{%0,%1,%2,%3}, {%4,%5,%6,%7}, {%8,%9}, {%0,%1,%2,%3};"
        : "+f"(c[0]), "+f"(c[1]), "+f"(c[2]), "+f"(c[3])
        : "r"(a0), "r"(a1), "r"(a2), "r"(a3), "r"(b0), "r"(b1));
}

// Pairwise named barrier: warps w and w+8 (64 threads), ids 1..8.
__device__ __forceinline__ void pair_bar(int pair) {
    asm volatile("bar.sync %0, 64;" :: "r"(pair + 1) : "memory");
}

// ===========================================================================
// Persistent fused SAGE layer GEMM: grid=148, all W images resident in SMEM.
// Warp-pair-private X fills with pairwise named barriers (round-14 verbatim).
// ===========================================================================
__global__ __launch_bounds__(512, 1) void sage_mma_kernel(
    const uint4* __restrict__ xhi4, const uint4* __restrict__ xlo4,
    const uint4* __restrict__ ahi4, const uint4* __restrict__ alo4,
    const uint4* __restrict__ wthi, const uint4* __restrict__ wtlo,
    const float* __restrict__ bias,
    float2* __restrict__ Out2,
    float* __restrict__ stats, int withBN)
{
    extern __shared__ char smem[];
    const uint32_t sbase = smem_u32(smem);
    const int tid = threadIdx.x;
    const int w = tid >> 5;
    const int lane = tid & 31;
    const int pairId = w & 7;
    const int m0 = pairId * 16;
    const int nhalf = w >> 3;

    float* s_sum = (float*)(smem + SM_STATS);
    float* s_sq = s_sum + 128;
    if (withBN && tid < 256) s_sum[tid] = 0.f;

    // ---- Load all four W images once (128 KB)
#pragma unroll
    for (int it = 0; it < 4; ++it) {
        int idx = tid + it * 512;
        ((uint4*)(smem + SM_W0HI))[idx] = __ldg(&wthi[idx]);
        ((uint4*)(smem + SM_W0LO))[idx] = __ldg(&wtlo[idx]);
        ((uint4*)(smem + SM_W1HI))[idx] = __ldg(&wthi[2048 + idx]);
        ((uint4*)(smem + SM_W1LO))[idx] = __ldg(&wtlo[2048 + idx]);
    }
    __syncthreads();

    const int aRow = m0 + (lane & 15);
    const uint32_t aBase = sbase + SM_XHI + (uint32_t)aRow * 256;
    const uint32_t aXor = (uint32_t)(aRow & 7) << 4;
    const uint32_t aSel = ((lane >> 4) & 1) * 16;
    const uint32_t bSel = ((lane >> 3) & 1) * 16;

    uint32_t bOff0[4], bXor[4];
#pragma unroll
    for (int ntp = 0; ntp < 4; ++ntp) {
        int bRow = nhalf * 64 + ntp * 16 + ((lane >> 4) & 1) * 8 + (lane & 7);
        bOff0[ntp] = sbase + SM_W0HI + (uint32_t)bRow * 256;
        bXor[ntp] = (uint32_t)(bRow & 7) << 4;
    }

    const uint32_t fillBase = (w < 8) ? SM_XHI : SM_XLO;

    for (int tile = blockIdx.x; tile < NTILES; tile += gridDim.x) {
        const int row0 = tile * TILE_M;

        float acc[8][4];
#pragma unroll
        for (int nt = 0; nt < 8; ++nt)
#pragma unroll
            for (int q = 0; q < 4; ++q) acc[nt][q] = 0.f;

#pragma unroll
        for (int pass = 0; pass < 2; ++pass) {
            const uint4* Src = (w < 8)
                ? ((pass == 0) ? xhi4 : ahi4)
                : ((pass == 0) ? xlo4 : alo4);

            pair_bar(pairId);

            // ---- Fill this pair's 16 rows of one image (8 uint4 per lane)
#pragma unroll
            for (int i = 0; i < 8; ++i) {
                int idx = lane + i * 32;
                int ml = idx >> 4;
                int ch = idx & 15;
                int m = m0 + ml;
                int gr = row0 + m;
                uint4 v = make_uint4(0, 0, 0, 0);
                if (gr < N_NODES) v = __ldg(&Src[gr * 16 + ch]);
                *(uint4*)(smem + fillBase + soff(m, ch * 16)) = v;
            }

            pair_bar(pairId);

            const uint32_t wShift = (uint32_t)pass * 65536;

            // ---- MMA main loop
#pragma unroll
            for (int ks = 0; ks < 8; ++ks) {
                uint32_t aoff = ((uint32_t)(ks * 32) + aSel) ^ aXor;
                uint32_t ah0, ah1, ah2, ah3, al0, al1, al2, al3;
                ldsm4(ah0, ah1, ah2, ah3, aBase + aoff);
                ldsm4(al0, al1, al2, al3, aBase + 32768 + aoff);
#pragma unroll
                for (int ntp = 0; ntp < 4; ++ntp) {
                    uint32_t bb = bOff0[ntp] + wShift;
                    uint32_t boff = ((uint32_t)(ks * 32) + bSel) ^ bXor[ntp];
                    uint32_t bh0, bh1, bh2, bh3, bl0, bl1, bl2, bl3;
                    ldsm4(bh0, bh1, bh2, bh3, bb + boff);
                    ldsm4(bl0, bl1, bl2, bl3, bb + 32768 + boff);
                    mma16816(acc[2 * ntp], ah0, ah1, ah2, ah3, bh0, bh1);
                    mma16816(acc[2 * ntp], ah0, ah1, ah2, ah3, bl0, bl1);
                    mma16816(acc[2 * ntp], al0, al1, al2, al3, bh0, bh1);
                    mma16816(acc[2 * ntp + 1], ah0, ah1, ah2, ah3, bh2, bh3);
                    mma16816(acc[2 * ntp + 1], ah0, ah1, ah2, ah3, bl2, bl3);
                    mma16816(acc[2 * ntp + 1], al0, al1, al2, al3, bh2, bh3);
                }
            }
        }

        // ---- Per-tile epilogue: bias + store + smem BN stats
        {
            int g = lane >> 2;
            int i = lane & 3;
            int grA = row0 + m0 + g;
            int grB = grA + 8;
            bool vA = grA < N_NODES, vB = grB < N_NODES;
#pragma unroll
            for (int nt = 0; nt < 8; ++nt) {
                int col = nhalf * 64 + nt * 8 + 2 * i;
                float2 bv = __ldg(&((const float2*)bias)[col >> 1]);
                float hA0 = acc[nt][0] + bv.x, hA1 = acc[nt][1] + bv.y;
                float hB0 = acc[nt][2] + bv.x, hB1 = acc[nt][3] + bv.y;
                if (vA) Out2[(size_t)grA * 64 + (col >> 1)] = make_float2(hA0, hA1);
                if (vB) Out2[(size_t)grB * 64 + (col >> 1)] = make_float2(hB0, hB1);
                if (withBN) {
                    float s0 = (vA ? hA0 : 0.f) + (vB ? hB0 : 0.f);
                    float s1 = (vA ? hA1 : 0.f) + (vB ? hB1 : 0.f);
                    float q0 = (vA ? hA0 * hA0 : 0.f) + (vB ? hB0 * hB0 : 0.f);
                    float q1 = (vA ? hA1 * hA1 : 0.f) + (vB ? hB1 * hB1 : 0.f);
#pragma unroll
                    for (int off = 16; off >= 4; off >>= 1) {
                        s0 += __shfl_down_sync(~0u, s0, off);
                        s1 += __shfl_down_sync(~0u, s1, off);
                        q0 += __shfl_down_sync(~0u, q0, off);
                        q1 += __shfl_down_sync(~0u, q1, off);
                    }
                    if (lane < 4) {
                        atomicAdd(&s_sum[col], s0);
                        atomicAdd(&s_sum[col + 1], s1);
                        atomicAdd(&s_sq[col], q0);
                        atomicAdd(&s_sq[col + 1], q1);
                    }
                }
            }
        }
    }

    if (withBN) {
        __syncthreads();
        if (tid < 128) {
            atomicAdd(&stats[tid], s_sum[tid]);
            atomicAdd(&stats[128 + tid], s_sq[tid]);
        }
    }
}

// ===========================================================================
extern "C" void kernel_launch(void* const* d_in, const int* in_sizes, int n_in,
                              void* d_out, int out_size) {
    const float* x   = (const float*)d_in[0];
    const int*   src = (const int*)  d_in[1];
    const int*   dst = (const int*)  d_in[2];
    const float* Ws1 = (const float*)d_in[3];
    const float* Wn1 = (const float*)d_in[4];
    const float* b1  = (const float*)d_in[5];
    const float* ga1 = (const float*)d_in[6];
    const float* be1 = (const float*)d_in[7];
    const float* Ws2 = (const float*)d_in[8];
    const float* Wn2 = (const float*)d_in[9];
    const float* b2  = (const float*)d_in[10];
    const float* ga2 = (const float*)d_in[11];
    const float* be2 = (const float*)d_in[12];
    const float* Ws3 = (const float*)d_in[13];
    const float* Wn3 = (const float*)d_in[14];
    const float* b3  = (const float*)d_in[15];
    float* out = (float*)d_out;

    float *bufA, *bufB, *invdeg, *stats;
    int *rowptr, *cursor, *csrsrc;
    uint4 *xhi, *xlo, *xh16, *agghi, *agglo, *wthi, *wtlo;
    cudaGetSymbolAddress((void**)&bufA,   g_bufA);
    cudaGetSymbolAddress((void**)&bufB,   g_bufB);
    cudaGetSymbolAddress((void**)&xhi,    g_xhi);
    cudaGetSymbolAddress((void**)&xlo,    g_xlo);
    cudaGetSymbolAddress((void**)&xh16,   g_xh16);
    cudaGetSymbolAddress((void**)&agghi,  g_agghi);
    cudaGetSymbolAddress((void**)&agglo,  g_agglo);
    cudaGetSymbolAddress((void**)&rowptr, g_rowptr);
    cudaGetSymbolAddress((void**)&cursor, g_cursor);
    cudaGetSymbolAddress((void**)&csrsrc, g_csrsrc);
    cudaGetSymbolAddress((void**)&invdeg, g_invdeg);
    cudaGetSymbolAddress((void**)&stats,  g_stats);
    cudaGetSymbolAddress((void**)&wthi,   g_wthi);
    cudaGetSymbolAddress((void**)&wtlo,   g_wtlo);

    cudaFuncSetAttribute(sage_mma_kernel,
                         cudaFuncAttributeMaxDynamicSharedMemorySize, SM_TOTAL);

    const int gthr_blocks = (N_NODES * 32 + 255) / 256;

    // Build CSR (round-11 scheme).
    zero_int_kernel<<<(N_NODES / 4 + 255) / 256, 256>>>((int4*)cursor, N_NODES / 4);
    hist_kernel<<<(N_EDGES / 4 + 255) / 256, 256>>>((const int4*)dst, cursor);
    scan_kernel<<<1, 1024>>>(cursor, rowptr, cursor, invdeg, stats);
    fill_kernel<<<(N_EDGES / 4 + 255) / 256, 256>>>((const int4*)src, (const int4*)dst,
                                                    cursor, csrsrc);

    // Layer 1 (stats -> g_stats[0:256))
    prep_kernel<<<PREP_BLOCKS + 16, 256>>>((const float4*)x, nullptr, nullptr, nullptr, 0,
                                           (uint2*)xhi, (uint2*)xlo, (uint2*)xh16,
                                           Ws1, Wn1, wthi, wtlo);
    gather_kernel<<<gthr_blocks, 256>>>((const uint2*)xh16, rowptr, csrsrc, invdeg,
                                        (uint2*)agghi, (uint2*)agglo);
    sage_mma_kernel<<<MMA_GRID, 512, SM_TOTAL>>>(
        xhi, xlo, agghi, agglo, wthi, wtlo, b1, (float2*)bufA, stats, 1);

    // Layer 2 (affine from stats[0:256), stats -> g_stats[256:512))
    prep_kernel<<<PREP_BLOCKS + 16, 256>>>((const float4*)bufA, stats, ga1, be1, 1,
                                           (uint2*)xhi, (uint2*)xlo, (uint2*)xh16,
                                           Ws2, Wn2, wthi, wtlo);
    gather_kernel<<<gthr_blocks, 256>>>((const uint2*)xh16, rowptr, csrsrc, invdeg,
                                        (uint2*)agghi, (uint2*)agglo);
    sage_mma_kernel<<<MMA_GRID, 512, SM_TOTAL>>>(
        xhi, xlo, agghi, agglo, wthi, wtlo, b2, (float2*)bufB, stats + 256, 1);

    // Layer 3 (affine from stats[256:512), no BN)
    prep_kernel<<<PREP_BLOCKS + 16, 256>>>((const float4*)bufB, stats + 256, ga2, be2, 1,
                                           (uint2*)xhi, (uint2*)xlo, (uint2*)xh16,
                                           Ws3, Wn3, wthi, wtlo);
    gather_kernel<<<gthr_blocks, 256>>>((const uint2*)xh16, rowptr, csrsrc, invdeg,
                                        (uint2*)agghi, (uint2*)agglo);
    sage_mma_kernel<<<MMA_GRID, 512, SM_TOTAL>>>(
        xhi, xlo, agghi, agglo, wthi, wtlo, b3, (float2*)out, stats, 0);
}